// round 1
// baseline (speedup 1.0000x reference)
#include <cuda_runtime.h>

#define NB  32
#define IDF 768
#define CDF 768
#define QL  1024
#define SL  128

// Scratch for the projected context sourceT[b][o][s]  (12.6 MB)
__device__ float g_srcT[(size_t)NB * IDF * SL];

// ---------------------------------------------------------------------------
// Kernel A: sourceT[b,o,s] = sum_c w[o,c] * ctx[b,c,s]
// One block per (o-tile of 128, b). 256 threads, 8x8 register tile, BK=16.
// ---------------------------------------------------------------------------
__global__ void __launch_bounds__(256, 1) proj_kernel(const float* __restrict__ w,
                                                      const float* __restrict__ ctx) {
    __shared__ float As[16 * 128];   // [c][o]  (transposed on store)
    __shared__ float Bs[16 * 128];   // [c][s]
    const int b  = blockIdx.y;
    const int o0 = blockIdx.x * 128;
    const int tid = threadIdx.x;
    const int tx = tid & 15, ty = tid >> 4;
    const float* ctxb = ctx + (size_t)b * CDF * SL;

    float acc[8][8];
#pragma unroll
    for (int i = 0; i < 8; i++)
#pragma unroll
        for (int j = 0; j < 8; j++) acc[i][j] = 0.f;

    for (int c0 = 0; c0 < CDF; c0 += 16) {
#pragma unroll
        for (int l = 0; l < 2; l++) {
            int li = tid * 2 + l;                 // 0..511 (float4 index)
            // A: w tile 128(o) x 16(c), transpose into As[c][o]
            int row = li >> 2;                    // o 0..127
            int col = (li & 3) * 4;               // c 0..12
            float4 v = *(const float4*)(w + (size_t)(o0 + row) * CDF + c0 + col);
            As[(col + 0) * 128 + row] = v.x;
            As[(col + 1) * 128 + row] = v.y;
            As[(col + 2) * 128 + row] = v.z;
            As[(col + 3) * 128 + row] = v.w;
            // B: ctx tile 16(c) x 128(s), direct
            int brow = li >> 5;                   // c 0..15
            int bcol = (li & 31) * 4;             // s
            *(float4*)(Bs + brow * 128 + bcol) =
                *(const float4*)(ctxb + (size_t)(c0 + brow) * SL + bcol);
        }
        __syncthreads();
#pragma unroll
        for (int k = 0; k < 16; k++) {
            float a[8], bb[8];
            *(float4*)(a)      = *(const float4*)(As + k * 128 + ty * 8);
            *(float4*)(a + 4)  = *(const float4*)(As + k * 128 + ty * 8 + 4);
            *(float4*)(bb)     = *(const float4*)(Bs + k * 128 + tx * 8);
            *(float4*)(bb + 4) = *(const float4*)(Bs + k * 128 + tx * 8 + 4);
#pragma unroll
            for (int i = 0; i < 8; i++)
#pragma unroll
                for (int j = 0; j < 8; j++)
                    acc[i][j] = fmaf(a[i], bb[j], acc[i][j]);
        }
        __syncthreads();
    }

    float* outb = g_srcT + ((size_t)b * IDF + o0) * SL;
#pragma unroll
    for (int i = 0; i < 8; i++)
#pragma unroll
        for (int j = 0; j < 8; j += 4)
            *(float4*)(outb + (size_t)(ty * 8 + i) * SL + tx * 8 + j) = *(float4*)(&acc[i][j]);
}

// ---------------------------------------------------------------------------
// Kernel B: fused attention per (b, q-tile of 128).
//  phase 1: logits[q][s] = sum_i target[i][q] * srcT[i][s]   (K=768)
//  phase 2: + mask*(-1e4), softmax over s, store TRANSPOSED attnT[s][q]
//           (attnT layout == attn_out layout; also k-major for phase 3)
//  phase 3: wc[i][q] = sum_s srcT[i][s] * attnT[s][q]        (6 chunks of 128 i)
// ---------------------------------------------------------------------------
__global__ void __launch_bounds__(256, 1) attn_kernel(const float* __restrict__ tgt_all,
                                                      const int* __restrict__ mask,
                                                      float* __restrict__ wc,
                                                      float* __restrict__ aout) {
    extern __shared__ float smem[];
    float* attnT = smem;               // [128 s][128 q], stride 128
    float* sTT   = smem + 128 * 128;   // [128 s][128 i], stride 129 (phase 3)
    float* As    = sTT;                // phase-1 alias: [16 k][128 q]
    float* Bs    = sTT + 16 * 128;     // phase-1 alias: [16 k][128 s]
    __shared__ int maskS[SL];

    const int b  = blockIdx.y;
    const int q0 = blockIdx.x * 128;
    const int tid = threadIdx.x;
    const int tx = tid & 15, ty = tid >> 4;
    const float* tgt = tgt_all + (size_t)b * IDF * QL;   // [i][q]
    const float* sT  = g_srcT  + (size_t)b * IDF * SL;   // [i][s]

    if (tid < SL) maskS[tid] = mask[b * SL + tid];

    // ---- phase 1: logits, rows q = ty*8+i, cols s = tx*8+j ----
    float acc[8][8];
#pragma unroll
    for (int i = 0; i < 8; i++)
#pragma unroll
        for (int j = 0; j < 8; j++) acc[i][j] = 0.f;

    for (int k0 = 0; k0 < IDF; k0 += 16) {
#pragma unroll
        for (int l = 0; l < 2; l++) {
            int li  = tid * 2 + l;        // 0..511
            int row = li >> 5;            // k 0..15
            int col = (li & 31) * 4;
            *(float4*)(As + row * 128 + col) =
                *(const float4*)(tgt + (size_t)(k0 + row) * QL + q0 + col);
            *(float4*)(Bs + row * 128 + col) =
                *(const float4*)(sT + (size_t)(k0 + row) * SL + col);
        }
        __syncthreads();
#pragma unroll
        for (int k = 0; k < 16; k++) {
            float a[8], bb[8];
            *(float4*)(a)      = *(const float4*)(As + k * 128 + ty * 8);
            *(float4*)(a + 4)  = *(const float4*)(As + k * 128 + ty * 8 + 4);
            *(float4*)(bb)     = *(const float4*)(Bs + k * 128 + tx * 8);
            *(float4*)(bb + 4) = *(const float4*)(Bs + k * 128 + tx * 8 + 4);
#pragma unroll
            for (int i = 0; i < 8; i++)
#pragma unroll
                for (int j = 0; j < 8; j++)
                    acc[i][j] = fmaf(a[i], bb[j], acc[i][j]);
        }
        __syncthreads();
    }

    // ---- phase 2: mask + transposed store + softmax over s ----
#pragma unroll
    for (int j = 0; j < 8; j++) {
        int s = tx * 8 + j;
        float mpen = -10000.0f * (float)maskS[s];
#pragma unroll
        for (int i = 0; i < 8; i++)
            attnT[s * 128 + ty * 8 + i] = acc[i][j] + mpen;
    }
    __syncthreads();

    {
        int q = tid >> 1;          // each column handled by 2 adjacent threads
        int h = tid & 1;
        float mx = -1e30f;
        for (int j = 0; j < 64; j++)
            mx = fmaxf(mx, attnT[(h * 64 + j) * 128 + q]);
        mx = fmaxf(mx, __shfl_xor_sync(0xffffffffu, mx, 1));
        float sum = 0.f;
        for (int j = 0; j < 64; j++) {
            int idx = (h * 64 + j) * 128 + q;
            float e = __expf(attnT[idx] - mx);
            attnT[idx] = e;
            sum += e;
        }
        sum += __shfl_xor_sync(0xffffffffu, sum, 1);
        float inv = 1.0f / sum;
        for (int j = 0; j < 64; j++)
            attnT[(h * 64 + j) * 128 + q] *= inv;
    }
    __syncthreads();

    // ---- attn_out[b][s][q0+q] = attnT[s][q] (already transposed) ----
    {
        float* ao = aout + (size_t)b * SL * QL + q0;
        for (int li = tid; li < 128 * 32; li += 256) {
            int s = li >> 5;
            int c = (li & 31) * 4;
            *(float4*)(ao + (size_t)s * QL + c) = *(const float4*)(attnT + s * 128 + c);
        }
    }

    // ---- phase 3: wc, 6 chunks of 128 i ----
    float* wcb = wc + (size_t)b * IDF * QL + q0;
    for (int i0 = 0; i0 < IDF; i0 += 128) {
        __syncthreads();   // prior sTT readers done (also first iter: attn_out writers)
        // sTT[s][i] = sT[i0+i][s], stride 129 avoids broadcast-row conflicts
        for (int li = tid; li < 128 * 32; li += 256) {
            int i = li >> 5;
            int c = (li & 31) * 4;
            float4 v = *(const float4*)(sT + (size_t)(i0 + i) * SL + c);
            sTT[(c + 0) * 129 + i] = v.x;
            sTT[(c + 1) * 129 + i] = v.y;
            sTT[(c + 2) * 129 + i] = v.z;
            sTT[(c + 3) * 129 + i] = v.w;
        }
        __syncthreads();

        float c8[8][8];
#pragma unroll
        for (int m = 0; m < 8; m++)
#pragma unroll
            for (int n = 0; n < 8; n++) c8[m][n] = 0.f;

#pragma unroll 4
        for (int k = 0; k < 128; k++) {
            float a[8], bb[8];
#pragma unroll
            for (int m = 0; m < 8; m++) a[m] = sTT[k * 129 + ty * 8 + m];
            *(float4*)(bb)     = *(const float4*)(attnT + k * 128 + tx * 8);
            *(float4*)(bb + 4) = *(const float4*)(attnT + k * 128 + tx * 8 + 4);
#pragma unroll
            for (int m = 0; m < 8; m++)
#pragma unroll
                for (int n = 0; n < 8; n++)
                    c8[m][n] = fmaf(a[m], bb[n], c8[m][n]);
        }
#pragma unroll
        for (int m = 0; m < 8; m++)
#pragma unroll
            for (int n = 0; n < 8; n += 4)
                *(float4*)(wcb + (size_t)(i0 + ty * 8 + m) * QL + tx * 8 + n) =
                    *(float4*)(&c8[m][n]);
    }
}

// ---------------------------------------------------------------------------
extern "C" void kernel_launch(void* const* d_in, const int* in_sizes, int n_in,
                              void* d_out, int out_size) {
    const float* input   = (const float*)d_in[0];   // [32,768,32,32]
    const float* context = (const float*)d_in[1];   // [32,768,128]
    const int*   mask    = (const int*)d_in[2];     // [32,128]
    const float* w_conv  = (const float*)d_in[3];   // [768,768]

    float* wc   = (float*)d_out;                    // [32,768,1024]
    float* aout = wc + (size_t)NB * IDF * QL;       // [32,128,1024]

    proj_kernel<<<dim3(IDF / 128, NB), 256>>>(w_conv, context);

    const size_t smem_b = (size_t)(128 * 128 + 128 * 129) * sizeof(float); // 131584
    cudaFuncSetAttribute(attn_kernel, cudaFuncAttributeMaxDynamicSharedMemorySize,
                         (int)smem_b);
    attn_kernel<<<dim3(QL / 128, NB), 256, smem_b>>>(input, mask, wc, aout);
}